// round 14
// baseline (speedup 1.0000x reference)
#include <cuda_runtime.h>

// Problem-instance capacities. Scratch is __device__ global (allocation-guard safe).
#define NK_CAP  2048
#define DIM_CAP 512
#define S_CAP   131072

__device__ float      g_cT[(size_t)NK_CAP * DIM_CAP];  // c transposed: [NK][DIM]
__device__ float4     g_w4[S_CAP];                     // per-sample weights (fallback path)
__device__ ulonglong2 g_wp[S_CAP][2];                  // pre-duplicated packed f32x2 weights
__device__ int        g_c0[S_CAP];                     // per-sample first column

typedef unsigned long long ull;

// ---- packed f32x2 helpers (sm_103a) ----
__device__ __forceinline__ ull fma2(ull a, ull b, ull c) {
    ull d; asm("fma.rn.f32x2 %0, %1, %2, %3;" : "=l"(d) : "l"(a), "l"(b), "l"(c));
    return d;
}
__device__ __forceinline__ ull mul2(ull a, ull b) {
    ull d; asm("mul.rn.f32x2 %0, %1, %2;" : "=l"(d) : "l"(a), "l"(b));
    return d;
}
__device__ __forceinline__ ull dup2(float x) {
    ull d; unsigned xi = __float_as_uint(x);
    asm("mov.b64 %0, {%1, %2};" : "=l"(d) : "r"(xi), "r"(xi));
    return d;
}

// ---------------------------------------------------------------------------
// Kernel A (block-specialized): transpose + per-sample weights, concurrently.
//   blocks [0, TB)     : transpose c[DIM][NK] -> g_cT[NK][DIM] with float4
//                        global reads (64-knot x 32-dim tiles)
//   blocks [TB, TB+WB) : one thread per sample: binary search + Cox-de Boor
// Weight semantics faithful to the reference's truncated in-place recursion:
//   final row F[i] = B3[i] (i < NK-3), B2[NK-3], B1[NK-2], B0[NK-1];
//   samples beyond the last proper span -> all-zero row; denom==0 -> weight 0.
// ---------------------------------------------------------------------------
__global__ __launch_bounds__(256)
void bspline_prep(const float* __restrict__ c,
                  const float* __restrict__ t,
                  const int*   __restrict__ delta_raw,
                  float* __restrict__ out,
                  int DIM, int NK, int S, int sp_count,
                  int TB, int TBx) {
    const int bid = blockIdx.x;
    if (bid < TB) {
        // ---------------- transpose role ----------------
        __shared__ float tile[64][33];   // [knot_local][dim_local]
        const int bx = bid % TBx, by = bid / TBx;
        const int x0 = bx * 64, y0 = by * 32;
        const int ltx = threadIdx.x & 15;   // knot quad index
        const int lty = threadIdx.x >> 4;   // 0..15 dim index
        const bool v4ok = ((NK & 3) == 0);
        #pragma unroll
        for (int q = 0; q < 2; q++) {
            const int y = y0 + lty + 16 * q;   // dim
            const int x = x0 + 4 * ltx;        // knot
            if (y < DIM) {
                if (v4ok && x + 3 < NK) {
                    const float4 v = *reinterpret_cast<const float4*>(
                        &c[(size_t)y * NK + x]);
                    tile[4 * ltx + 0][lty + 16 * q] = v.x;
                    tile[4 * ltx + 1][lty + 16 * q] = v.y;
                    tile[4 * ltx + 2][lty + 16 * q] = v.z;
                    tile[4 * ltx + 3][lty + 16 * q] = v.w;
                } else {
                    #pragma unroll
                    for (int j = 0; j < 4; j++)
                        if (x + j < NK)
                            tile[4 * ltx + j][lty + 16 * q] =
                                c[(size_t)y * NK + x + j];
                }
            }
        }
        __syncthreads();
        const int wtx = threadIdx.x & 31;   // dim
        const int wty = threadIdx.x >> 5;   // 0..7
        const int xd = y0 + wtx;
        if (xd < DIM) {
            #pragma unroll
            for (int i = wty; i < 64; i += 8) {
                const int yk = x0 + i;
                if (yk < NK)
                    g_cT[(size_t)yk * DIM + xd] = tile[i][wtx];
            }
        }
        return;
    }

    // ---------------- weights role ----------------
    const int sidx = (bid - TB) * 256 + threadIdx.x;
    if (sidx >= S || sidx >= S_CAP) return;

    // delta arrives as int32 (python int); tolerate float32 encoding too.
    int iv = *delta_raw;
    float delta = (iv > 0 && iv < (1 << 20)) ? (float)iv : __int_as_float(iv);

    const float s = (float)sidx * delta;
    if (sp_count) out[sidx] = s;  // sample_points region

    float w0 = 0.f, w1 = 0.f, w2 = 0.f, w3 = 0.f;
    int c0 = 0;

    // ub = first index with t[ub] > s  (span j = ub + 3 in padded knots)
    int lo = 0, hi = NK;
    while (lo < hi) {
        int mid = (lo + hi) >> 1;
        if (__ldg(&t[mid]) > s) hi = mid; else lo = mid + 1;
    }
    const int ub = lo;
    if (ub <= NK - 4) {
        const int j = ub + 3;  // padded-knot span: k[j] <= s < k[j+1]
        float k[8];
        #pragma unroll
        for (int m = 1; m <= 6; m++) {
            int gi = j - 3 + m;
            k[m] = (gi < 4) ? 0.0f : __ldg(&t[gi - 4]);
        }
        const float Km2 = k[1], Km1 = k[2], K0 = k[3];
        const float K1  = k[4], K2  = k[5], K3 = k[6];

        auto rat = [](float num, float den) -> float {
            return (den == 0.0f) ? 0.0f : num / den;
        };

        // degree 1
        const float b1a = rat(K1 - s, K1 - K0);
        const float b1b = rat(s - K0, K1 - K0);
        // degree 2
        const float b2a = rat(K1 - s, K1 - Km1) * b1a;
        const float b2b = rat(s - Km1, K1 - Km1) * b1a
                        + rat(K2 - s, K2 - K0)   * b1b;
        const float b2c = rat(s - K0, K2 - K0)   * b1b;
        // degree 3
        const float b3a = rat(K1 - s, K1 - Km2) * b2a;
        const float b3b = rat(s - Km2, K1 - Km2) * b2a
                        + rat(K2 - s, K2 - Km1)  * b2b;
        const float b3c = rat(s - Km1, K2 - Km1) * b2b
                        + rat(K3 - s, K3 - K0)   * b2c;
        const float b3d = rat(s - K0, K3 - K0)   * b2c;

        const float b3v[4] = {b3a, b3b, b3c, b3d};
        const float b2v[3] = {b2a, b2b, b2c};
        const float b1v[2] = {b1a, b1b};
        float wv[4];
        #pragma unroll
        for (int m = 0; m < 4; m++) {
            const int col = j - 3 + m;
            float f = b3v[m];                                    // proper deg-3
            if (col == NK - 3)      f = b2v[m > 0 ? m - 1 : 0];  // stale deg-2
            else if (col == NK - 2) f = b1v[m > 1 ? m - 2 : 0];  // stale deg-1
            else if (col == NK - 1) f = 1.0f;                    // stale deg-0
            wv[m] = f;
        }
        w0 = wv[0]; w1 = wv[1]; w2 = wv[2]; w3 = wv[3];
        c0 = j - 3;
    }
    g_w4[sidx] = make_float4(w0, w1, w2, w3);
    ulonglong2 p0; p0.x = dup2(w0); p0.y = dup2(w1);
    ulonglong2 p1; p1.x = dup2(w2); p1.y = dup2(w3);
    g_wp[sidx][0] = p0;
    g_wp[sidx][1] = p1;
    g_c0[sidx] = c0;
}

// ---------------------------------------------------------------------------
// Kernel B (fast path): fused epilogue, segment-structured with speculative
// row prefetch and BALANCED sample partitioning. Grid is sized to exactly
// fill the chip in ONE wave (12 blocks/SM at 42 regs); each block gets
// floor/ceil(S/G) consecutive samples -> no wave-quantization tail.
// Register p holds row (cur+4): loaded at each span change, consumed at the
// next one. The "+1 shift consumes p" path requires c0+4 <= NK-1, so a
// clamped (stale-content) p is never consumed.
// ---------------------------------------------------------------------------
#define SPB_MAX 40

__global__ __launch_bounds__(1024)
void bspline_fused(float* __restrict__ out, int sp_count, int DIM4,
                   int S, int NK) {
    __shared__ ulonglong2 swp[SPB_MAX][2];
    __shared__ int        sc[SPB_MAX];

    const int tid = threadIdx.x;
    const int G   = gridDim.x;
    const int bid = blockIdx.x;

    // balanced partition: first r blocks get q+1 samples, rest get q
    const int q  = S / G;
    const int r  = S - q * G;
    const int s0 = bid * q + (bid < r ? bid : r);
    const int nS = q + (bid < r ? 1 : 0);

    for (int u = tid; u < 2 * nS; u += blockDim.x) {
        const int sm = u >> 1, half = u & 1;
        swp[sm][half] = g_wp[s0 + sm][half];
    }
    for (int u = tid; u < nS; u += blockDim.x)
        sc[u] = g_c0[s0 + u];
    __syncthreads();

    if (nS == 0) return;

    const ulonglong2* __restrict__ cTu =
        reinterpret_cast<const ulonglong2*>(g_cT);
    ulonglong2* __restrict__ o =
        reinterpret_cast<ulonglong2*>(out + sp_count) + (size_t)s0 * DIM4 + tid;

    int cur = sc[0];
    {
        // cold start: 4 rows + speculative next row, issued together (MLP=5)
        const ulonglong2* b = cTu + (size_t)cur * DIM4 + tid;
        ulonglong2 v0 = b[0], v1 = b[DIM4], v2 = b[2 * DIM4], v3 = b[3 * DIM4];
        int pr = cur + 4; if (pr > NK - 1) pr = NK - 1;
        ulonglong2 p = cTu[(size_t)pr * DIM4 + tid];

        int i = 0;
        #pragma unroll 1
        while (i < nS) {
            // find end of current span segment (sc uniform across block)
            int e = i + 1;
            while (e < nS && sc[e] == cur) ++e;
            // branch-free burst over the segment
            #pragma unroll 1
            for (; i < e; ++i) {
                const ulonglong2 wA = swp[i][0];
                const ulonglong2 wB = swp[i][1];
                ulonglong2 acc;
                acc.x = fma2(wA.x, v0.x,
                        fma2(wA.y, v1.x,
                        fma2(wB.x, v2.x, mul2(wB.y, v3.x))));
                acc.y = fma2(wA.x, v0.y,
                        fma2(wA.y, v1.y,
                        fma2(wB.x, v2.y, mul2(wB.y, v3.y))));
                o[(size_t)i * DIM4] = acc;
            }
            if (i < nS) {
                const int cn = sc[i];
                if (cn == cur + 1) {            // common: one-span step
                    v0 = v1; v1 = v2; v2 = v3; v3 = p;
                } else {                        // rare: multi-step / reset
                    const ulonglong2* nb = cTu + (size_t)cn * DIM4 + tid;
                    v0 = nb[0]; v1 = nb[DIM4];
                    v2 = nb[2 * DIM4]; v3 = nb[3 * DIM4];
                }
                cur = cn;
                int pn = cur + 4; if (pn > NK - 1) pn = NK - 1;
                p = cTu[(size_t)pn * DIM4 + tid];  // hidden behind next segment
            }
        }
    }
}

// ---------------------------------------------------------------------------
// Scalar fallback: one thread per output element. Shape-safe.
// ---------------------------------------------------------------------------
__global__ __launch_bounds__(256)
void bspline_stream_scalar(float* __restrict__ out, int sp_count,
                           int DIM, long long total) {
    const long long idx = (long long)blockIdx.x * 256 + threadIdx.x;
    if (idx >= total) return;
    const int smp = (int)(idx / DIM);
    const int d   = (int)(idx - (long long)smp * DIM);
    const float4 w  = g_w4[smp];
    const int    c0 = g_c0[smp];
    float r = w.x * g_cT[(size_t)(c0 + 0) * DIM + d]
            + w.y * g_cT[(size_t)(c0 + 1) * DIM + d]
            + w.z * g_cT[(size_t)(c0 + 2) * DIM + d]
            + w.w * g_cT[(size_t)(c0 + 3) * DIM + d];
    out[(size_t)sp_count + (size_t)smp * DIM + d] = r;
}

// ---------------------------------------------------------------------------
extern "C" void kernel_launch(void* const* d_in, const int* in_sizes, int n_in,
                              void* d_out, int out_size) {
    const float* t     = (const float*)d_in[0];
    const float* c     = (const float*)d_in[1];
    const int*   delta = (const int*)d_in[2];
    float*       out   = (float*)d_out;

    const int NK  = in_sizes[0];        // 2048
    const int DIM = in_sizes[1] / NK;   // 512

    // Output = concat(sample_points[S], spline[S, DIM]) -> out_size = S*(DIM+1).
    int S, sp_count;
    if (out_size % (DIM + 1) == 0) { S = out_size / (DIM + 1); sp_count = S; }
    else                           { S = out_size / DIM;       sp_count = 0; }

    // Kernel A: transpose + weights in one launch (independent roles overlap)
    const int TBx = (NK + 63) / 64;
    const int TBy = (DIM + 31) / 32;
    const int TB  = TBx * TBy;
    const int WB  = (S + 255) / 256;
    bspline_prep<<<TB + WB, 256>>>(c, t, delta, out, DIM, NK, S, sp_count,
                                   TB, TBx);

    // Kernel B: fused register-cached epilogue, single balanced wave
    const int DIM4 = DIM >> 2;
    const bool vec = ((DIM & 7) == 0) && ((sp_count & 3) == 0) &&
                     (DIM4 >= 32) && (DIM4 <= 1024) && (S <= S_CAP);
    if (vec) {
        // 12 resident blocks/SM at 42 regs x 128 thr; 148 SMs -> one full wave.
        int G = 12 * 148;
        // capacity guard: every block's share must fit the shared arrays
        int minG = (S + SPB_MAX - 1) / SPB_MAX;
        if (G < minG) G = minG;
        if (G > S) G = S;                   // at least 1 sample per block
        if (G < 1) G = 1;
        bspline_fused<<<G, DIM4>>>(out, sp_count, DIM4, S, NK);
    } else {
        const long long total = (long long)S * DIM;
        bspline_stream_scalar<<<(int)((total + 255) / 256), 256>>>(out, sp_count,
                                                                   DIM, total);
    }
}